// round 9
// baseline (speedup 1.0000x reference)
#include <cuda_runtime.h>
#include <cuda_fp16.h>
#include <cstdint>

#define NP 100000
#define ND 20000
#define DD 128
#define EP 1600000
#define ED 800000

#define BM 64
#define BK 16
#define NB 391              // (NP+255)/256 scan blocks

typedef unsigned long long u64;

// ---- scratch (device globals; allocation APIs forbidden) ----
// g_pcnt/g_dcnt are zero on load and re-zeroed by k_scan1 after use each call.
__device__ int    g_pcnt[NP];
__device__ int    g_dcnt[NP];
__device__ int    g_pstart[NP + 1];
__device__ int    g_dstart[NP + 1];
__device__ int    g_pcur[NP];
__device__ int    g_dcur[NP];
__device__ int    g_pbsum[NB], g_dbsum[NB];
__device__ int    g_pboff[NB], g_dboff[NB];
__device__ int    g_plist[EP];        // src per ppi edge, grouped by dst
__device__ int    g_dlist[ED];        // drug per dti edge, grouped by prot
__device__ float  g_dinv[NP];
__device__ float  g_cinv[NP];
__device__ __half g_h1s[(size_t)NP * DD];   // fp16: dinv[r] * (x @ W_gcn)[r]
__device__ __half g_msgs[(size_t)ND * DD];  // fp16: x_drug @ W_td + b_td
__device__ float  g_h3[(size_t)NP * DD];    // fp32: x @ W_pr + biases + 1e-6

// ---- f32x2 packed-FMA helpers ----
__device__ __forceinline__ u64 pk2(float lo, float hi) {
    u64 r;
    asm("mov.b64 %0, {%1, %2};" : "=l"(r) : "f"(lo), "f"(hi));
    return r;
}
__device__ __forceinline__ void upk2(float& lo, float& hi, u64 v) {
    asm("mov.b64 {%0, %1}, %2;" : "=f"(lo), "=f"(hi) : "l"(v));
}
__device__ __forceinline__ void fma2(u64& acc, u64 a, u64 b) {
    asm("fma.rn.f32x2 %0, %1, %2, %0;" : "+l"(acc) : "l"(a), "l"(b));
}

// accumulate fp16 row fragment (uint2 = 4 halves) into float4
__device__ __forceinline__ void acc_h4(float4& acc, uint2 u) {
    __half2 a = *(__half2*)&u.x;
    __half2 b = *(__half2*)&u.y;
    float2 fa = __half22float2(a);
    float2 fb = __half22float2(b);
    acc.x += fa.x; acc.y += fa.y; acc.z += fb.x; acc.w += fb.y;
}

// ------------------------------------------------------------------
// CSR build
// ------------------------------------------------------------------
__global__ __launch_bounds__(256) void k_count(const int* __restrict__ pdst,
                                               const int* __restrict__ dprot) {
    int e = blockIdx.x * 256 + threadIdx.x;
    if (e < EP) atomicAdd(&g_pcnt[__ldg(pdst + e)], 1);
    else if (e < EP + ED) atomicAdd(&g_dcnt[__ldg(dprot + (e - EP))], 1);
}

// counts -> dinv/cinv + per-block exclusive starts + block sums; zeroes counts
// (self-clean for the next kernel_launch invocation)
__global__ __launch_bounds__(256) void k_scan1() {
    __shared__ int sp[256], sd[256];
    int t = threadIdx.x;
    int i = blockIdx.x * 256 + t;
    int vp = (i < NP) ? g_pcnt[i] : 0;
    int vd = (i < NP) ? g_dcnt[i] : 0;
    if (i < NP) {
        g_pcnt[i] = 0; g_dcnt[i] = 0;
        g_dinv[i] = rsqrtf((float)(vp + 1));        // +1 self loop
        g_cinv[i] = 1.0f / fmaxf((float)vd, 1.0f);  // mean divisor
    }
    sp[t] = vp; sd[t] = vd;
    __syncthreads();
#pragma unroll
    for (int off = 1; off < 256; off <<= 1) {
        int ap = 0, ad = 0;
        if (t >= off) { ap = sp[t - off]; ad = sd[t - off]; }
        __syncthreads();
        sp[t] += ap; sd[t] += ad;
        __syncthreads();
    }
    if (i < NP) { g_pstart[i] = sp[t] - vp; g_dstart[i] = sd[t] - vd; }
    if (t == 255) { g_pbsum[blockIdx.x] = sp[255]; g_dbsum[blockIdx.x] = sd[255]; }
}

__global__ __launch_bounds__(512) void k_scan2() {
    __shared__ int sp[512], sd[512];
    int t = threadIdx.x;
    int vp = (t < NB) ? g_pbsum[t] : 0;
    int vd = (t < NB) ? g_dbsum[t] : 0;
    sp[t] = vp; sd[t] = vd;
    __syncthreads();
#pragma unroll
    for (int off = 1; off < 512; off <<= 1) {
        int ap = 0, ad = 0;
        if (t >= off) { ap = sp[t - off]; ad = sd[t - off]; }
        __syncthreads();
        sp[t] += ap; sd[t] += ad;
        __syncthreads();
    }
    if (t < NB) { g_pboff[t] = sp[t] - vp; g_dboff[t] = sd[t] - vd; }
}

__global__ __launch_bounds__(256) void k_scan3() {
    int i = blockIdx.x * 256 + threadIdx.x;
    if (i < NP) {
        int ps = g_pstart[i] + g_pboff[blockIdx.x];
        int ds = g_dstart[i] + g_dboff[blockIdx.x];
        g_pstart[i] = ps; g_pcur[i] = ps;
        g_dstart[i] = ds; g_dcur[i] = ds;
    }
    if (i == 0) { g_pstart[NP] = EP; g_dstart[NP] = ED; }
}

__global__ __launch_bounds__(256) void k_fill(const int* __restrict__ psrc,
                                              const int* __restrict__ pdst,
                                              const int* __restrict__ ddrug,
                                              const int* __restrict__ dprot) {
    int e = blockIdx.x * 256 + threadIdx.x;
    if (e < EP) {
        int c = __ldg(pdst + e);
        int pos = atomicAdd(&g_pcur[c], 1);
        g_plist[pos] = __ldg(psrc + e);
    } else if (e < EP + ED) {
        int ee = e - EP;
        int c = __ldg(dprot + ee);
        int pos = atomicAdd(&g_dcur[c], 1);
        g_dlist[pos] = __ldg(ddrug + ee);
    }
}

// ------------------------------------------------------------------
// Drug GEMM (FFMA2, zero-mov inner loop): g_msgs = fp16(x_drug @ W_td + b_td)
// A tile stored as pre-duplicated (a,a) u64 pairs; B pairs read via ulonglong2.
// warp w -> rows w*8..w*8+7; lane l -> cols 4l..4l+3.
// ------------------------------------------------------------------
__global__ __launch_bounds__(256) void k_gemm_drug(
    const float* __restrict__ A, const float* __restrict__ B,
    const float* __restrict__ bias) {
    __shared__ u64 Xs2[BK][BM];      // (a,a) duplicated pairs
    __shared__ float Bs[BK][DD];
    int tid = threadIdx.x;
    int lane = tid & 31;
    int w = tid >> 5;
    int rbase = w * 8;
    int row0 = blockIdx.x * BM;

    u64 acc[8][2];
#pragma unroll
    for (int i = 0; i < 8; i++) { acc[i][0] = 0ull; acc[i][1] = 0ull; }

    for (int k0 = 0; k0 < DD; k0 += BK) {
        {   // A tile 64x16 -> duplicated pairs
            int r = tid >> 2;
            int kc = (tid & 3) * 4;
            float4 v = make_float4(0.f, 0.f, 0.f, 0.f);
            int gr = row0 + r;
            if (gr < ND) v = *(const float4*)(A + (size_t)gr * DD + k0 + kc);
            Xs2[kc + 0][r] = pk2(v.x, v.x);
            Xs2[kc + 1][r] = pk2(v.y, v.y);
            Xs2[kc + 2][r] = pk2(v.z, v.z);
            Xs2[kc + 3][r] = pk2(v.w, v.w);
        }
#pragma unroll
        for (int u = 0; u < 2; u++) {  // B tile 16x128
            int idx = tid + u * 256;
            int k = idx >> 5, c4 = idx & 31;
            *(float4*)&Bs[k][c4 * 4] =
                *(const float4*)(B + (size_t)(k0 + k) * DD + c4 * 4);
        }
        __syncthreads();
#pragma unroll
        for (int k = 0; k < BK; k++) {
            ulonglong2 x01 = *(const ulonglong2*)&Xs2[k][rbase];
            ulonglong2 x23 = *(const ulonglong2*)&Xs2[k][rbase + 2];
            ulonglong2 x45 = *(const ulonglong2*)&Xs2[k][rbase + 4];
            ulonglong2 x67 = *(const ulonglong2*)&Xs2[k][rbase + 6];
            u64 pa[8] = {x01.x, x01.y, x23.x, x23.y, x45.x, x45.y, x67.x, x67.y};
            ulonglong2 bb = *(const ulonglong2*)&Bs[k][lane * 4];
#pragma unroll
            for (int i = 0; i < 8; i++) {
                fma2(acc[i][0], pa[i], bb.x);
                fma2(acc[i][1], pa[i], bb.y);
            }
        }
        __syncthreads();
    }

    float b0 = __ldg(bias + lane * 4),     b1 = __ldg(bias + lane * 4 + 1);
    float b2 = __ldg(bias + lane * 4 + 2), b3 = __ldg(bias + lane * 4 + 3);
#pragma unroll
    for (int i = 0; i < 8; i++) {
        int r = row0 + rbase + i;
        if (r < ND) {
            float l0, h0, l1, h1;
            upk2(l0, h0, acc[i][0]); upk2(l1, h1, acc[i][1]);
            __half2 hh[2];
            hh[0] = __floats2half2_rn(l0 + b0, h0 + b1);
            hh[1] = __floats2half2_rn(l1 + b2, h1 + b3);
            *(uint2*)(g_msgs + (size_t)r * DD + lane * 4) = *(uint2*)hh;
        }
    }
}

// ------------------------------------------------------------------
// Pre-GEMM (FFMA2, zero-mov inner loop, single A tile, dual B):
//   g_h1s = fp16( dinv .* (x @ W_gcn) )
//   g_h3  = x @ W_pr + b_pr + b_gcn + 1e-6   (fp32)
// ------------------------------------------------------------------
__global__ __launch_bounds__(256) void k_pre(
    const float* __restrict__ A,    // x_prot
    const float* __restrict__ Bg,   // W_gcn
    const float* __restrict__ Bx,   // W_pr
    const float* __restrict__ bg, const float* __restrict__ bx) {
    __shared__ u64 Xs2[BK][BM];      // (a,a) duplicated pairs
    __shared__ float Bs1[BK][DD], Bs2[BK][DD];
    int tid = threadIdx.x;
    int lane = tid & 31;
    int w = tid >> 5;
    int rbase = w * 8;
    int row0 = blockIdx.x * BM;

    u64 acc1[8][2], acc2[8][2];
#pragma unroll
    for (int i = 0; i < 8; i++) {
        acc1[i][0] = 0ull; acc1[i][1] = 0ull;
        acc2[i][0] = 0ull; acc2[i][1] = 0ull;
    }

    for (int k0 = 0; k0 < DD; k0 += BK) {
        {
            int r = tid >> 2;
            int kc = (tid & 3) * 4;
            int gr = row0 + r;
            float4 v = make_float4(0.f, 0.f, 0.f, 0.f);
            if (gr < NP) v = *(const float4*)(A + (size_t)gr * DD + k0 + kc);
            Xs2[kc + 0][r] = pk2(v.x, v.x);
            Xs2[kc + 1][r] = pk2(v.y, v.y);
            Xs2[kc + 2][r] = pk2(v.z, v.z);
            Xs2[kc + 3][r] = pk2(v.w, v.w);
        }
#pragma unroll
        for (int u = 0; u < 2; u++) {
            int idx = tid + u * 256;
            int k = idx >> 5, c4 = idx & 31;
            *(float4*)&Bs1[k][c4 * 4] =
                *(const float4*)(Bg + (size_t)(k0 + k) * DD + c4 * 4);
            *(float4*)&Bs2[k][c4 * 4] =
                *(const float4*)(Bx + (size_t)(k0 + k) * DD + c4 * 4);
        }
        __syncthreads();
#pragma unroll
        for (int k = 0; k < BK; k++) {
            ulonglong2 x01 = *(const ulonglong2*)&Xs2[k][rbase];
            ulonglong2 x23 = *(const ulonglong2*)&Xs2[k][rbase + 2];
            ulonglong2 x45 = *(const ulonglong2*)&Xs2[k][rbase + 4];
            ulonglong2 x67 = *(const ulonglong2*)&Xs2[k][rbase + 6];
            u64 pa[8] = {x01.x, x01.y, x23.x, x23.y, x45.x, x45.y, x67.x, x67.y};
            ulonglong2 bgp = *(const ulonglong2*)&Bs1[k][lane * 4];
            ulonglong2 bxp = *(const ulonglong2*)&Bs2[k][lane * 4];
#pragma unroll
            for (int i = 0; i < 8; i++) {
                fma2(acc1[i][0], pa[i], bgp.x);
                fma2(acc1[i][1], pa[i], bgp.y);
                fma2(acc2[i][0], pa[i], bxp.x);
                fma2(acc2[i][1], pa[i], bxp.y);
            }
        }
        __syncthreads();
    }

    float bs0 = __ldg(bg + lane * 4)     + __ldg(bx + lane * 4)     + 1e-6f;
    float bs1 = __ldg(bg + lane * 4 + 1) + __ldg(bx + lane * 4 + 1) + 1e-6f;
    float bs2 = __ldg(bg + lane * 4 + 2) + __ldg(bx + lane * 4 + 2) + 1e-6f;
    float bs3 = __ldg(bg + lane * 4 + 3) + __ldg(bx + lane * 4 + 3) + 1e-6f;

#pragma unroll
    for (int i = 0; i < 8; i++) {
        int r = row0 + rbase + i;
        if (r < NP) {
            float dv = __ldg(g_dinv + r);
            float l0, h0, l1, h1;
            upk2(l0, h0, acc1[i][0]); upk2(l1, h1, acc1[i][1]);
            __half2 hh[2];
            hh[0] = __floats2half2_rn(l0 * dv, h0 * dv);
            hh[1] = __floats2half2_rn(l1 * dv, h1 * dv);
            *(uint2*)(g_h1s + (size_t)r * DD + lane * 4) = *(uint2*)hh;

            upk2(l0, h0, acc2[i][0]); upk2(l1, h1, acc2[i][1]);
            *(float4*)(g_h3 + (size_t)r * DD + lane * 4) =
                make_float4(l0 + bs0, h0 + bs1, l1 + bs2, h1 + bs3);
        }
    }
}

// ------------------------------------------------------------------
// Fused gather + LayerNorm: one warp per protein row.
// fp16 payloads (8 B / lane / edge), fp32 accumulation.
// ------------------------------------------------------------------
__global__ __launch_bounds__(256) void k_gather_ln(float* __restrict__ out) {
    int c = blockIdx.x * 8 + (threadIdx.x >> 5);
    if (c >= NP) return;
    int lane = threadIdx.x & 31;

    // PPI aggregate over pre-scaled h1s (self term included)
    float4 acc = make_float4(0.f, 0.f, 0.f, 0.f);
    acc_h4(acc, __ldg((const uint2*)(g_h1s + (size_t)c * DD) + lane));

    int i = __ldg(g_pstart + c), e = __ldg(g_pstart + c + 1);
    for (; i + 7 < e; i += 8) {
        int r[8];
        uint2 u[8];
#pragma unroll
        for (int t = 0; t < 8; t++) r[t] = __ldg(g_plist + i + t);
#pragma unroll
        for (int t = 0; t < 8; t++)
            u[t] = __ldg((const uint2*)(g_h1s + (size_t)r[t] * DD) + lane);
#pragma unroll
        for (int t = 0; t < 8; t++) acc_h4(acc, u[t]);
    }
    for (; i < e; i++) {
        int r0 = __ldg(g_plist + i);
        acc_h4(acc, __ldg((const uint2*)(g_h1s + (size_t)r0 * DD) + lane));
    }

    // DTI aggregate
    float4 accB = make_float4(0.f, 0.f, 0.f, 0.f);
    i = __ldg(g_dstart + c); e = __ldg(g_dstart + c + 1);
    for (; i + 3 < e; i += 4) {
        int d[4];
        uint2 u[4];
#pragma unroll
        for (int t = 0; t < 4; t++) d[t] = __ldg(g_dlist + i + t);
#pragma unroll
        for (int t = 0; t < 4; t++)
            u[t] = __ldg((const uint2*)(g_msgs + (size_t)d[t] * DD) + lane);
#pragma unroll
        for (int t = 0; t < 4; t++) acc_h4(accB, u[t]);
    }
    for (; i < e; i++) {
        int d0 = __ldg(g_dlist + i);
        acc_h4(accB, __ldg((const uint2*)(g_msgs + (size_t)d0 * DD) + lane));
    }

    float dc = __ldg(g_dinv + c);
    float ci = __ldg(g_cinv + c);
    float4 h3 = __ldg((const float4*)(g_h3 + (size_t)c * DD) + lane);
    float4 y;
    y.x = dc * acc.x + ci * accB.x + h3.x;
    y.y = dc * acc.y + ci * accB.y + h3.y;
    y.z = dc * acc.z + ci * accB.z + h3.z;
    y.w = dc * acc.w + ci * accB.w + h3.w;

    // LayerNorm over the 32-lane row (lane owns 4 consecutive cols)
    float s = (y.x + y.y) + (y.z + y.w);
#pragma unroll
    for (int o = 16; o > 0; o >>= 1) s += __shfl_xor_sync(0xffffffffu, s, o);
    float mu = s * (1.0f / DD);
    float dx = y.x - mu, dy = y.y - mu, dz = y.z - mu, dw = y.w - mu;
    float q = (dx * dx + dy * dy) + (dz * dz + dw * dw);
#pragma unroll
    for (int o = 16; o > 0; o >>= 1) q += __shfl_xor_sync(0xffffffffu, q, o);
    float inv = rsqrtf(q * (1.0f / DD) + 1e-5f);
    float4 o4 = make_float4(dx * inv, dy * inv, dz * inv, dw * inv);
    ((float4*)(out + (size_t)c * DD))[lane] = o4;
}

// ------------------------------------------------------------------
extern "C" void kernel_launch(void* const* d_in, const int* in_sizes, int n_in,
                              void* d_out, int out_size) {
    const float* x_prot = (const float*)d_in[0];
    const float* x_drug = (const float*)d_in[1];
    const float* W_gcn  = (const float*)d_in[2];
    const float* b_gcn  = (const float*)d_in[3];
    const float* W_td   = (const float*)d_in[4];
    const float* b_td   = (const float*)d_in[5];
    const float* W_pr   = (const float*)d_in[6];
    const float* b_pr   = (const float*)d_in[7];
    const int*   ppi    = (const int*)d_in[8];   // [2, EP]: src = ppi, dst = ppi+EP
    const int*   dti_d  = (const int*)d_in[9];
    const int*   dti_p  = (const int*)d_in[10];
    float* out = (float*)d_out;

    k_count<<<(EP + ED + 255) / 256, 256>>>(ppi + EP, dti_p);            // 1
    k_scan1<<<NB, 256>>>();                                              // 2 (dinv/cinv here)
    k_gemm_drug<<<(ND + BM - 1) / BM, 256>>>(x_drug, W_td, b_td);        // 3
    k_pre<<<(NP + BM - 1) / BM, 256>>>(x_prot, W_gcn, W_pr, b_gcn, b_pr); // 4 (profiled)
    k_scan2<<<1, 512>>>();                                               // 5
    k_scan3<<<NB, 256>>>();                                              // 6
    k_fill<<<(EP + ED + 255) / 256, 256>>>(ppi, ppi + EP, dti_d, dti_p); // 7
    k_gather_ln<<<(NP + 7) / 8, 256>>>(out);                             // 8
}

// round 10
// speedup vs baseline: 1.1677x; 1.1677x over previous
#include <cuda_runtime.h>
#include <cuda_fp16.h>
#include <cstdint>

#define NP 100000
#define ND 20000
#define DD 128
#define EP 1600000
#define ED 800000

#define BM 64
#define BK 16
#define NB 391              // (NP+255)/256 scan blocks
#define PRE_BLOCKS ((NP + BM - 1) / BM)   // 1563
#define DRUG_BLOCKS ((ND + BM - 1) / BM)  // 313

typedef unsigned long long u64;

// ---- scratch (device globals; allocation APIs forbidden) ----
// g_pcnt/g_dcnt are zero on load and re-zeroed by k_scan1 after use each call.
__device__ int    g_pcnt[NP];
__device__ int    g_dcnt[NP];
__device__ int    g_pstart[NP + 1];
__device__ int    g_dstart[NP + 1];
__device__ int    g_pcur[NP];
__device__ int    g_dcur[NP];
__device__ int    g_pbsum[NB], g_dbsum[NB];
__device__ int    g_pboff[NB], g_dboff[NB];
__device__ int    g_plist[EP];        // src per ppi edge, grouped by dst
__device__ int    g_dlist[ED];        // drug per dti edge, grouped by prot
__device__ float  g_dinv[NP];
__device__ float  g_cinv[NP];
__device__ __half g_h1s[(size_t)NP * DD];   // fp16: dinv[r] * (x @ W_gcn)[r]
__device__ __half g_msgs[(size_t)ND * DD];  // fp16: x_drug @ W_td + b_td
__device__ float  g_h3[(size_t)NP * DD];    // fp32: x @ W_pr + biases + 1e-6

// ---- f32x2 packed-FMA helpers ----
__device__ __forceinline__ u64 pk2(float lo, float hi) {
    u64 r;
    asm("mov.b64 %0, {%1, %2};" : "=l"(r) : "f"(lo), "f"(hi));
    return r;
}
__device__ __forceinline__ void upk2(float& lo, float& hi, u64 v) {
    asm("mov.b64 {%0, %1}, %2;" : "=f"(lo), "=f"(hi) : "l"(v));
}
__device__ __forceinline__ void fma2(u64& acc, u64 a, u64 b) {
    asm("fma.rn.f32x2 %0, %1, %2, %0;" : "+l"(acc) : "l"(a), "l"(b));
}

// accumulate fp16 row fragment (uint2 = 4 halves) into float4
__device__ __forceinline__ void acc_h4(float4& acc, uint2 u) {
    __half2 a = *(__half2*)&u.x;
    __half2 b = *(__half2*)&u.y;
    float2 fa = __half22float2(a);
    float2 fb = __half22float2(b);
    acc.x += fa.x; acc.y += fa.y; acc.z += fb.x; acc.w += fb.y;
}

// ------------------------------------------------------------------
// CSR build
// ------------------------------------------------------------------
__global__ __launch_bounds__(256) void k_count(const int* __restrict__ pdst,
                                               const int* __restrict__ dprot) {
    int e = blockIdx.x * 256 + threadIdx.x;
    if (e < EP) atomicAdd(&g_pcnt[__ldg(pdst + e)], 1);
    else if (e < EP + ED) atomicAdd(&g_dcnt[__ldg(dprot + (e - EP))], 1);
}

// counts -> dinv/cinv + per-block exclusive starts + block sums; zeroes counts
// (self-clean for the next kernel_launch invocation)
__global__ __launch_bounds__(256) void k_scan1() {
    __shared__ int sp[256], sd[256];
    int t = threadIdx.x;
    int i = blockIdx.x * 256 + t;
    int vp = (i < NP) ? g_pcnt[i] : 0;
    int vd = (i < NP) ? g_dcnt[i] : 0;
    if (i < NP) {
        g_pcnt[i] = 0; g_dcnt[i] = 0;
        g_dinv[i] = rsqrtf((float)(vp + 1));        // +1 self loop
        g_cinv[i] = 1.0f / fmaxf((float)vd, 1.0f);  // mean divisor
    }
    sp[t] = vp; sd[t] = vd;
    __syncthreads();
#pragma unroll
    for (int off = 1; off < 256; off <<= 1) {
        int ap = 0, ad = 0;
        if (t >= off) { ap = sp[t - off]; ad = sd[t - off]; }
        __syncthreads();
        sp[t] += ap; sd[t] += ad;
        __syncthreads();
    }
    if (i < NP) { g_pstart[i] = sp[t] - vp; g_dstart[i] = sd[t] - vd; }
    if (t == 255) { g_pbsum[blockIdx.x] = sp[255]; g_dbsum[blockIdx.x] = sd[255]; }
}

__global__ __launch_bounds__(512) void k_scan2() {
    __shared__ int sp[512], sd[512];
    int t = threadIdx.x;
    int vp = (t < NB) ? g_pbsum[t] : 0;
    int vd = (t < NB) ? g_dbsum[t] : 0;
    sp[t] = vp; sd[t] = vd;
    __syncthreads();
#pragma unroll
    for (int off = 1; off < 512; off <<= 1) {
        int ap = 0, ad = 0;
        if (t >= off) { ap = sp[t - off]; ad = sd[t - off]; }
        __syncthreads();
        sp[t] += ap; sd[t] += ad;
        __syncthreads();
    }
    if (t < NB) { g_pboff[t] = sp[t] - vp; g_dboff[t] = sd[t] - vd; }
}

__global__ __launch_bounds__(256) void k_scan3() {
    int i = blockIdx.x * 256 + threadIdx.x;
    if (i < NP) {
        int ps = g_pstart[i] + g_pboff[blockIdx.x];
        int ds = g_dstart[i] + g_dboff[blockIdx.x];
        g_pstart[i] = ps; g_pcur[i] = ps;
        g_dstart[i] = ds; g_dcur[i] = ds;
    }
    if (i == 0) { g_pstart[NP] = EP; g_dstart[NP] = ED; }
}

__global__ __launch_bounds__(256) void k_fill(const int* __restrict__ psrc,
                                              const int* __restrict__ pdst,
                                              const int* __restrict__ ddrug,
                                              const int* __restrict__ dprot) {
    int e = blockIdx.x * 256 + threadIdx.x;
    if (e < EP) {
        int c = __ldg(pdst + e);
        int pos = atomicAdd(&g_pcur[c], 1);
        g_plist[pos] = __ldg(psrc + e);
    } else if (e < EP + ED) {
        int ee = e - EP;
        int c = __ldg(dprot + ee);
        int pos = atomicAdd(&g_dcur[c], 1);
        g_dlist[pos] = __ldg(ddrug + ee);
    }
}

// ------------------------------------------------------------------
// Fused GEMM kernel (R8 inner-loop form: float A tile, packs in loop).
// Blocks [0, PRE_BLOCKS):      protein dual GEMM -> g_h1s (fp16), g_h3 (fp32)
// Blocks [PRE_BLOCKS, +DRUG):  drug GEMM         -> g_msgs (fp16)
// warp w -> rows w*8..w*8+7; lane l -> cols 4l..4l+3 (conflict-free).
// ------------------------------------------------------------------
__global__ __launch_bounds__(256) void k_mm(
    const float* __restrict__ A,    // x_prot
    const float* __restrict__ Bg,   // W_gcn
    const float* __restrict__ Bx,   // W_pr
    const float* __restrict__ bg, const float* __restrict__ bx,
    const float* __restrict__ Ad,   // x_drug
    const float* __restrict__ Bt,   // W_td
    const float* __restrict__ bt) {
    __shared__ float Xs[BK][BM];
    __shared__ float Bs1[BK][DD], Bs2[BK][DD];
    int tid = threadIdx.x;
    int lane = tid & 31;
    int w = tid >> 5;
    int rbase = w * 8;

    if (blockIdx.x < PRE_BLOCKS) {
        // ---------------- protein dual GEMM ----------------
        int row0 = blockIdx.x * BM;

        u64 acc1[8][2], acc2[8][2];
#pragma unroll
        for (int i = 0; i < 8; i++) {
            acc1[i][0] = 0ull; acc1[i][1] = 0ull;
            acc2[i][0] = 0ull; acc2[i][1] = 0ull;
        }

        for (int k0 = 0; k0 < DD; k0 += BK) {
            {
                int r = tid >> 2;
                int kc = (tid & 3) * 4;
                int gr = row0 + r;
                float4 v = make_float4(0.f, 0.f, 0.f, 0.f);
                if (gr < NP) v = *(const float4*)(A + (size_t)gr * DD + k0 + kc);
                Xs[kc + 0][r] = v.x; Xs[kc + 1][r] = v.y;
                Xs[kc + 2][r] = v.z; Xs[kc + 3][r] = v.w;
            }
#pragma unroll
            for (int u = 0; u < 2; u++) {
                int idx = tid + u * 256;
                int k = idx >> 5, c4 = idx & 31;
                *(float4*)&Bs1[k][c4 * 4] =
                    *(const float4*)(Bg + (size_t)(k0 + k) * DD + c4 * 4);
                *(float4*)&Bs2[k][c4 * 4] =
                    *(const float4*)(Bx + (size_t)(k0 + k) * DD + c4 * 4);
            }
            __syncthreads();
#pragma unroll
            for (int k = 0; k < BK; k++) {
                float4 a0 = *(const float4*)&Xs[k][rbase];
                float4 a1 = *(const float4*)&Xs[k][rbase + 4];
                float4 bgv = *(const float4*)&Bs1[k][lane * 4];
                float4 bxv = *(const float4*)&Bs2[k][lane * 4];
                u64 pg0 = pk2(bgv.x, bgv.y), pg1 = pk2(bgv.z, bgv.w);
                u64 px0 = pk2(bxv.x, bxv.y), px1 = pk2(bxv.z, bxv.w);
                float ar[8] = {a0.x, a0.y, a0.z, a0.w, a1.x, a1.y, a1.z, a1.w};
#pragma unroll
                for (int i = 0; i < 8; i++) {
                    u64 pa = pk2(ar[i], ar[i]);
                    fma2(acc1[i][0], pa, pg0);
                    fma2(acc1[i][1], pa, pg1);
                    fma2(acc2[i][0], pa, px0);
                    fma2(acc2[i][1], pa, px1);
                }
            }
            __syncthreads();
        }

        float bs0 = __ldg(bg + lane * 4)     + __ldg(bx + lane * 4)     + 1e-6f;
        float bs1 = __ldg(bg + lane * 4 + 1) + __ldg(bx + lane * 4 + 1) + 1e-6f;
        float bs2 = __ldg(bg + lane * 4 + 2) + __ldg(bx + lane * 4 + 2) + 1e-6f;
        float bs3 = __ldg(bg + lane * 4 + 3) + __ldg(bx + lane * 4 + 3) + 1e-6f;

#pragma unroll
        for (int i = 0; i < 8; i++) {
            int r = row0 + rbase + i;
            if (r < NP) {
                float dv = __ldg(g_dinv + r);
                float l0, h0, l1, h1;
                upk2(l0, h0, acc1[i][0]); upk2(l1, h1, acc1[i][1]);
                __half2 hh[2];
                hh[0] = __floats2half2_rn(l0 * dv, h0 * dv);
                hh[1] = __floats2half2_rn(l1 * dv, h1 * dv);
                *(uint2*)(g_h1s + (size_t)r * DD + lane * 4) = *(uint2*)hh;

                upk2(l0, h0, acc2[i][0]); upk2(l1, h1, acc2[i][1]);
                *(float4*)(g_h3 + (size_t)r * DD + lane * 4) =
                    make_float4(l0 + bs0, h0 + bs1, l1 + bs2, h1 + bs3);
            }
        }
    } else {
        // ---------------- drug GEMM ----------------
        int row0 = (blockIdx.x - PRE_BLOCKS) * BM;

        u64 acc[8][2];
#pragma unroll
        for (int i = 0; i < 8; i++) { acc[i][0] = 0ull; acc[i][1] = 0ull; }

        for (int k0 = 0; k0 < DD; k0 += BK) {
            {
                int r = tid >> 2;
                int kc = (tid & 3) * 4;
                float4 v = make_float4(0.f, 0.f, 0.f, 0.f);
                int gr = row0 + r;
                if (gr < ND) v = *(const float4*)(Ad + (size_t)gr * DD + k0 + kc);
                Xs[kc + 0][r] = v.x; Xs[kc + 1][r] = v.y;
                Xs[kc + 2][r] = v.z; Xs[kc + 3][r] = v.w;
            }
#pragma unroll
            for (int u = 0; u < 2; u++) {
                int idx = tid + u * 256;
                int k = idx >> 5, c4 = idx & 31;
                *(float4*)&Bs1[k][c4 * 4] =
                    *(const float4*)(Bt + (size_t)(k0 + k) * DD + c4 * 4);
            }
            __syncthreads();
#pragma unroll
            for (int k = 0; k < BK; k++) {
                float4 a0 = *(const float4*)&Xs[k][rbase];
                float4 a1 = *(const float4*)&Xs[k][rbase + 4];
                float4 b = *(const float4*)&Bs1[k][lane * 4];
                u64 pb0 = pk2(b.x, b.y), pb1 = pk2(b.z, b.w);
                float ar[8] = {a0.x, a0.y, a0.z, a0.w, a1.x, a1.y, a1.z, a1.w};
#pragma unroll
                for (int i = 0; i < 8; i++) {
                    u64 pa = pk2(ar[i], ar[i]);
                    fma2(acc[i][0], pa, pb0);
                    fma2(acc[i][1], pa, pb1);
                }
            }
            __syncthreads();
        }

        float b0 = __ldg(bt + lane * 4),     b1 = __ldg(bt + lane * 4 + 1);
        float b2 = __ldg(bt + lane * 4 + 2), b3 = __ldg(bt + lane * 4 + 3);
#pragma unroll
        for (int i = 0; i < 8; i++) {
            int r = row0 + rbase + i;
            if (r < ND) {
                float l0, h0, l1, h1;
                upk2(l0, h0, acc[i][0]); upk2(l1, h1, acc[i][1]);
                __half2 hh[2];
                hh[0] = __floats2half2_rn(l0 + b0, h0 + b1);
                hh[1] = __floats2half2_rn(l1 + b2, h1 + b3);
                *(uint2*)(g_msgs + (size_t)r * DD + lane * 4) = *(uint2*)hh;
            }
        }
    }
}

// ------------------------------------------------------------------
// Fused gather + LayerNorm: one warp per protein row.
// fp16 payloads (8 B / lane / edge), fp32 accumulation.
// ------------------------------------------------------------------
__global__ __launch_bounds__(256) void k_gather_ln(float* __restrict__ out) {
    int c = blockIdx.x * 8 + (threadIdx.x >> 5);
    if (c >= NP) return;
    int lane = threadIdx.x & 31;

    // PPI aggregate over pre-scaled h1s (self term included)
    float4 acc = make_float4(0.f, 0.f, 0.f, 0.f);
    acc_h4(acc, __ldg((const uint2*)(g_h1s + (size_t)c * DD) + lane));

    int i = __ldg(g_pstart + c), e = __ldg(g_pstart + c + 1);
    for (; i + 7 < e; i += 8) {
        int r[8];
        uint2 u[8];
#pragma unroll
        for (int t = 0; t < 8; t++) r[t] = __ldg(g_plist + i + t);
#pragma unroll
        for (int t = 0; t < 8; t++)
            u[t] = __ldg((const uint2*)(g_h1s + (size_t)r[t] * DD) + lane);
#pragma unroll
        for (int t = 0; t < 8; t++) acc_h4(acc, u[t]);
    }
    for (; i < e; i++) {
        int r0 = __ldg(g_plist + i);
        acc_h4(acc, __ldg((const uint2*)(g_h1s + (size_t)r0 * DD) + lane));
    }

    // DTI aggregate
    float4 accB = make_float4(0.f, 0.f, 0.f, 0.f);
    i = __ldg(g_dstart + c); e = __ldg(g_dstart + c + 1);
    for (; i + 3 < e; i += 4) {
        int d[4];
        uint2 u[4];
#pragma unroll
        for (int t = 0; t < 4; t++) d[t] = __ldg(g_dlist + i + t);
#pragma unroll
        for (int t = 0; t < 4; t++)
            u[t] = __ldg((const uint2*)(g_msgs + (size_t)d[t] * DD) + lane);
#pragma unroll
        for (int t = 0; t < 4; t++) acc_h4(accB, u[t]);
    }
    for (; i < e; i++) {
        int d0 = __ldg(g_dlist + i);
        acc_h4(accB, __ldg((const uint2*)(g_msgs + (size_t)d0 * DD) + lane));
    }

    float dc = __ldg(g_dinv + c);
    float ci = __ldg(g_cinv + c);
    float4 h3 = __ldg((const float4*)(g_h3 + (size_t)c * DD) + lane);
    float4 y;
    y.x = dc * acc.x + ci * accB.x + h3.x;
    y.y = dc * acc.y + ci * accB.y + h3.y;
    y.z = dc * acc.z + ci * accB.z + h3.z;
    y.w = dc * acc.w + ci * accB.w + h3.w;

    // LayerNorm over the 32-lane row (lane owns 4 consecutive cols)
    float s = (y.x + y.y) + (y.z + y.w);
#pragma unroll
    for (int o = 16; o > 0; o >>= 1) s += __shfl_xor_sync(0xffffffffu, s, o);
    float mu = s * (1.0f / DD);
    float dx = y.x - mu, dy = y.y - mu, dz = y.z - mu, dw = y.w - mu;
    float q = (dx * dx + dy * dy) + (dz * dz + dw * dw);
#pragma unroll
    for (int o = 16; o > 0; o >>= 1) q += __shfl_xor_sync(0xffffffffu, q, o);
    float inv = rsqrtf(q * (1.0f / DD) + 1e-5f);
    float4 o4 = make_float4(dx * inv, dy * inv, dz * inv, dw * inv);
    ((float4*)(out + (size_t)c * DD))[lane] = o4;
}

// ------------------------------------------------------------------
extern "C" void kernel_launch(void* const* d_in, const int* in_sizes, int n_in,
                              void* d_out, int out_size) {
    const float* x_prot = (const float*)d_in[0];
    const float* x_drug = (const float*)d_in[1];
    const float* W_gcn  = (const float*)d_in[2];
    const float* b_gcn  = (const float*)d_in[3];
    const float* W_td   = (const float*)d_in[4];
    const float* b_td   = (const float*)d_in[5];
    const float* W_pr   = (const float*)d_in[6];
    const float* b_pr   = (const float*)d_in[7];
    const int*   ppi    = (const int*)d_in[8];   // [2, EP]: src = ppi, dst = ppi+EP
    const int*   dti_d  = (const int*)d_in[9];
    const int*   dti_p  = (const int*)d_in[10];
    float* out = (float*)d_out;

    k_count<<<(EP + ED + 255) / 256, 256>>>(ppi + EP, dti_p);            // 1
    k_scan1<<<NB, 256>>>();                                              // 2 (dinv/cinv here)
    k_scan2<<<1, 512>>>();                                               // 3
    k_mm<<<PRE_BLOCKS + DRUG_BLOCKS, 256>>>(x_prot, W_gcn, W_pr,         // 4 (profiled)
                                            b_gcn, b_pr, x_drug, W_td, b_td);
    k_scan3<<<NB, 256>>>();                                              // 5
    k_fill<<<(EP + ED + 255) / 256, 256>>>(ppi, ppi + EP, dti_d, dti_p); // 6
    k_gather_ln<<<(NP + 7) / 8, 256>>>(out);                             // 7
}

// round 11
// speedup vs baseline: 1.1718x; 1.0035x over previous
#include <cuda_runtime.h>
#include <cuda_fp16.h>
#include <cstdint>

#define NP 100000
#define ND 20000
#define DD 128
#define EP 1600000
#define ED 800000

#define BM 64
#define BK 16
#define NB 391              // (NP+255)/256 scan blocks
#define PRE_BLOCKS ((NP + BM - 1) / BM)   // 1563
#define DRUG_BLOCKS ((ND + BM - 1) / BM)  // 313

typedef unsigned long long u64;

// ---- scratch (device globals; allocation APIs forbidden) ----
// g_pcnt/g_dcnt are zero on load and re-zeroed by k_scan1 after use each call.
__device__ int    g_pcnt[NP];
__device__ int    g_dcnt[NP];
__device__ int    g_pstart[NP + 1];
__device__ int    g_dstart[NP + 1];
__device__ int    g_pcur[NP];
__device__ int    g_dcur[NP];
__device__ int    g_pbsum[NB], g_dbsum[NB];
__device__ int    g_pboff[NB], g_dboff[NB];
__device__ int    g_plist[EP];        // src per ppi edge, grouped by dst
__device__ int    g_dlist[ED];        // drug per dti edge, grouped by prot
__device__ float  g_dinv[NP];
__device__ float  g_cinv[NP];
__device__ __half g_h1s[(size_t)NP * DD];   // fp16: dinv[r] * (x @ W_gcn)[r]
__device__ __half g_msgs[(size_t)ND * DD];  // fp16: x_drug @ W_td + b_td
__device__ float  g_h3[(size_t)NP * DD];    // fp32: x @ W_pr + biases + 1e-6

// ---- f32x2 packed-FMA helpers ----
__device__ __forceinline__ u64 pk2(float lo, float hi) {
    u64 r;
    asm("mov.b64 %0, {%1, %2};" : "=l"(r) : "f"(lo), "f"(hi));
    return r;
}
__device__ __forceinline__ void upk2(float& lo, float& hi, u64 v) {
    asm("mov.b64 {%0, %1}, %2;" : "=f"(lo), "=f"(hi) : "l"(v));
}
__device__ __forceinline__ void fma2(u64& acc, u64 a, u64 b) {
    asm("fma.rn.f32x2 %0, %1, %2, %0;" : "+l"(acc) : "l"(a), "l"(b));
}

// accumulate fp16 row fragment (uint2 = 4 halves) into float4
__device__ __forceinline__ void acc_h4(float4& acc, uint2 u) {
    __half2 a = *(__half2*)&u.x;
    __half2 b = *(__half2*)&u.y;
    float2 fa = __half22float2(a);
    float2 fb = __half22float2(b);
    acc.x += fa.x; acc.y += fa.y; acc.z += fb.x; acc.w += fb.y;
}

// ------------------------------------------------------------------
// CSR build
// ------------------------------------------------------------------
__global__ __launch_bounds__(256) void k_count(const int* __restrict__ pdst,
                                               const int* __restrict__ dprot) {
    int e = blockIdx.x * 256 + threadIdx.x;
    if (e < EP) atomicAdd(&g_pcnt[__ldg(pdst + e)], 1);
    else if (e < EP + ED) atomicAdd(&g_dcnt[__ldg(dprot + (e - EP))], 1);
}

// counts -> dinv/cinv + per-block exclusive starts + block sums; zeroes counts
// (self-clean for the next kernel_launch invocation)
__global__ __launch_bounds__(256) void k_scan1() {
    __shared__ int sp[256], sd[256];
    int t = threadIdx.x;
    int i = blockIdx.x * 256 + t;
    int vp = (i < NP) ? g_pcnt[i] : 0;
    int vd = (i < NP) ? g_dcnt[i] : 0;
    if (i < NP) {
        g_pcnt[i] = 0; g_dcnt[i] = 0;
        g_dinv[i] = rsqrtf((float)(vp + 1));        // +1 self loop
        g_cinv[i] = 1.0f / fmaxf((float)vd, 1.0f);  // mean divisor
    }
    sp[t] = vp; sd[t] = vd;
    __syncthreads();
#pragma unroll
    for (int off = 1; off < 256; off <<= 1) {
        int ap = 0, ad = 0;
        if (t >= off) { ap = sp[t - off]; ad = sd[t - off]; }
        __syncthreads();
        sp[t] += ap; sd[t] += ad;
        __syncthreads();
    }
    if (i < NP) { g_pstart[i] = sp[t] - vp; g_dstart[i] = sd[t] - vd; }
    if (t == 255) { g_pbsum[blockIdx.x] = sp[255]; g_dbsum[blockIdx.x] = sd[255]; }
}

__global__ __launch_bounds__(512) void k_scan2() {
    __shared__ int sp[512], sd[512];
    int t = threadIdx.x;
    int vp = (t < NB) ? g_pbsum[t] : 0;
    int vd = (t < NB) ? g_dbsum[t] : 0;
    sp[t] = vp; sd[t] = vd;
    __syncthreads();
#pragma unroll
    for (int off = 1; off < 512; off <<= 1) {
        int ap = 0, ad = 0;
        if (t >= off) { ap = sp[t - off]; ad = sd[t - off]; }
        __syncthreads();
        sp[t] += ap; sd[t] += ad;
        __syncthreads();
    }
    if (t < NB) { g_pboff[t] = sp[t] - vp; g_dboff[t] = sd[t] - vd; }
}

__global__ __launch_bounds__(256) void k_scan3() {
    int i = blockIdx.x * 256 + threadIdx.x;
    if (i < NP) {
        int ps = g_pstart[i] + g_pboff[blockIdx.x];
        int ds = g_dstart[i] + g_dboff[blockIdx.x];
        g_pstart[i] = ps; g_pcur[i] = ps;
        g_dstart[i] = ds; g_dcur[i] = ds;
    }
    if (i == 0) { g_pstart[NP] = EP; g_dstart[NP] = ED; }
}

__global__ __launch_bounds__(256) void k_fill(const int* __restrict__ psrc,
                                              const int* __restrict__ pdst,
                                              const int* __restrict__ ddrug,
                                              const int* __restrict__ dprot) {
    int e = blockIdx.x * 256 + threadIdx.x;
    if (e < EP) {
        int c = __ldg(pdst + e);
        int pos = atomicAdd(&g_pcur[c], 1);
        g_plist[pos] = __ldg(psrc + e);
    } else if (e < EP + ED) {
        int ee = e - EP;
        int c = __ldg(dprot + ee);
        int pos = atomicAdd(&g_dcur[c], 1);
        g_dlist[pos] = __ldg(ddrug + ee);
    }
}

// ------------------------------------------------------------------
// Fused GEMM kernel. Packed-pair layout: the f32x2 lane-pair carries TWO
// consecutive A rows (read free as u64 from the row-contiguous Xs tile);
// B scalars are duplicated via 4 packs per matrix. 44 issues/k vs 48.
// Blocks [0, PRE_BLOCKS):      protein dual GEMM -> g_h1s (fp16), g_h3 (fp32)
// Blocks [PRE_BLOCKS, +DRUG):  drug GEMM         -> g_msgs (fp16)
// warp w -> rows w*8..w*8+7; lane l -> cols 4l..4l+3 (conflict-free).
// ------------------------------------------------------------------
__global__ __launch_bounds__(256) void k_mm(
    const float* __restrict__ A,    // x_prot
    const float* __restrict__ Bg,   // W_gcn
    const float* __restrict__ Bx,   // W_pr
    const float* __restrict__ bg, const float* __restrict__ bx,
    const float* __restrict__ Ad,   // x_drug
    const float* __restrict__ Bt,   // W_td
    const float* __restrict__ bt) {
    __shared__ float Xs[BK][BM];
    __shared__ float Bs1[BK][DD], Bs2[BK][DD];
    int tid = threadIdx.x;
    int lane = tid & 31;
    int w = tid >> 5;
    int rbase = w * 8;

    if (blockIdx.x < PRE_BLOCKS) {
        // ---------------- protein dual GEMM ----------------
        int row0 = blockIdx.x * BM;

        // acc[rp][c]: row-pair rp (rows rbase+2rp, +1), col c (lane*4+c)
        u64 acc1[4][4], acc2[4][4];
#pragma unroll
        for (int i = 0; i < 4; i++)
#pragma unroll
            for (int j = 0; j < 4; j++) { acc1[i][j] = 0ull; acc2[i][j] = 0ull; }

        for (int k0 = 0; k0 < DD; k0 += BK) {
            {
                int r = tid >> 2;
                int kc = (tid & 3) * 4;
                int gr = row0 + r;
                float4 v = make_float4(0.f, 0.f, 0.f, 0.f);
                if (gr < NP) v = *(const float4*)(A + (size_t)gr * DD + k0 + kc);
                Xs[kc + 0][r] = v.x; Xs[kc + 1][r] = v.y;
                Xs[kc + 2][r] = v.z; Xs[kc + 3][r] = v.w;
            }
#pragma unroll
            for (int u = 0; u < 2; u++) {
                int idx = tid + u * 256;
                int k = idx >> 5, c4 = idx & 31;
                *(float4*)&Bs1[k][c4 * 4] =
                    *(const float4*)(Bg + (size_t)(k0 + k) * DD + c4 * 4);
                *(float4*)&Bs2[k][c4 * 4] =
                    *(const float4*)(Bx + (size_t)(k0 + k) * DD + c4 * 4);
            }
            __syncthreads();
#pragma unroll
            for (int k = 0; k < BK; k++) {
                // free row-pairs: Xs[k][] is contiguous in r
                ulonglong2 xa = *(const ulonglong2*)&Xs[k][rbase];
                ulonglong2 xb = *(const ulonglong2*)&Xs[k][rbase + 4];
                u64 pa[4] = {xa.x, xa.y, xb.x, xb.y};
                float4 bgv = *(const float4*)&Bs1[k][lane * 4];
                float4 bxv = *(const float4*)&Bs2[k][lane * 4];
                u64 pg[4] = {pk2(bgv.x, bgv.x), pk2(bgv.y, bgv.y),
                             pk2(bgv.z, bgv.z), pk2(bgv.w, bgv.w)};
                u64 px[4] = {pk2(bxv.x, bxv.x), pk2(bxv.y, bxv.y),
                             pk2(bxv.z, bxv.z), pk2(bxv.w, bxv.w)};
#pragma unroll
                for (int rp = 0; rp < 4; rp++)
#pragma unroll
                    for (int c = 0; c < 4; c++) {
                        fma2(acc1[rp][c], pa[rp], pg[c]);
                        fma2(acc2[rp][c], pa[rp], px[c]);
                    }
            }
            __syncthreads();
        }

        float bs0 = __ldg(bg + lane * 4)     + __ldg(bx + lane * 4)     + 1e-6f;
        float bs1 = __ldg(bg + lane * 4 + 1) + __ldg(bx + lane * 4 + 1) + 1e-6f;
        float bs2 = __ldg(bg + lane * 4 + 2) + __ldg(bx + lane * 4 + 2) + 1e-6f;
        float bs3 = __ldg(bg + lane * 4 + 3) + __ldg(bx + lane * 4 + 3) + 1e-6f;

#pragma unroll
        for (int rp = 0; rp < 4; rp++) {
            int re = row0 + rbase + 2 * rp;   // even row (pair lo)
            int ro = re + 1;                  // odd row (pair hi)
            float e0, o0, e1, o1, e2, o2, e3, o3;
            upk2(e0, o0, acc1[rp][0]); upk2(e1, o1, acc1[rp][1]);
            upk2(e2, o2, acc1[rp][2]); upk2(e3, o3, acc1[rp][3]);
            if (re < NP) {
                float dv = __ldg(g_dinv + re);
                __half2 hh[2] = {__floats2half2_rn(e0 * dv, e1 * dv),
                                 __floats2half2_rn(e2 * dv, e3 * dv)};
                *(uint2*)(g_h1s + (size_t)re * DD + lane * 4) = *(uint2*)hh;
            }
            if (ro < NP) {
                float dv = __ldg(g_dinv + ro);
                __half2 hh[2] = {__floats2half2_rn(o0 * dv, o1 * dv),
                                 __floats2half2_rn(o2 * dv, o3 * dv)};
                *(uint2*)(g_h1s + (size_t)ro * DD + lane * 4) = *(uint2*)hh;
            }
            upk2(e0, o0, acc2[rp][0]); upk2(e1, o1, acc2[rp][1]);
            upk2(e2, o2, acc2[rp][2]); upk2(e3, o3, acc2[rp][3]);
            if (re < NP)
                *(float4*)(g_h3 + (size_t)re * DD + lane * 4) =
                    make_float4(e0 + bs0, e1 + bs1, e2 + bs2, e3 + bs3);
            if (ro < NP)
                *(float4*)(g_h3 + (size_t)ro * DD + lane * 4) =
                    make_float4(o0 + bs0, o1 + bs1, o2 + bs2, o3 + bs3);
        }
    } else {
        // ---------------- drug GEMM ----------------
        int row0 = (blockIdx.x - PRE_BLOCKS) * BM;

        u64 acc[4][4];
#pragma unroll
        for (int i = 0; i < 4; i++)
#pragma unroll
            for (int j = 0; j < 4; j++) acc[i][j] = 0ull;

        for (int k0 = 0; k0 < DD; k0 += BK) {
            {
                int r = tid >> 2;
                int kc = (tid & 3) * 4;
                float4 v = make_float4(0.f, 0.f, 0.f, 0.f);
                int gr = row0 + r;
                if (gr < ND) v = *(const float4*)(Ad + (size_t)gr * DD + k0 + kc);
                Xs[kc + 0][r] = v.x; Xs[kc + 1][r] = v.y;
                Xs[kc + 2][r] = v.z; Xs[kc + 3][r] = v.w;
            }
#pragma unroll
            for (int u = 0; u < 2; u++) {
                int idx = tid + u * 256;
                int k = idx >> 5, c4 = idx & 31;
                *(float4*)&Bs1[k][c4 * 4] =
                    *(const float4*)(Bt + (size_t)(k0 + k) * DD + c4 * 4);
            }
            __syncthreads();
#pragma unroll
            for (int k = 0; k < BK; k++) {
                ulonglong2 xa = *(const ulonglong2*)&Xs[k][rbase];
                ulonglong2 xb = *(const ulonglong2*)&Xs[k][rbase + 4];
                u64 pa[4] = {xa.x, xa.y, xb.x, xb.y};
                float4 b = *(const float4*)&Bs1[k][lane * 4];
                u64 pb[4] = {pk2(b.x, b.x), pk2(b.y, b.y),
                             pk2(b.z, b.z), pk2(b.w, b.w)};
#pragma unroll
                for (int rp = 0; rp < 4; rp++)
#pragma unroll
                    for (int c = 0; c < 4; c++)
                        fma2(acc[rp][c], pa[rp], pb[c]);
            }
            __syncthreads();
        }

        float b0 = __ldg(bt + lane * 4),     b1 = __ldg(bt + lane * 4 + 1);
        float b2 = __ldg(bt + lane * 4 + 2), b3 = __ldg(bt + lane * 4 + 3);
#pragma unroll
        for (int rp = 0; rp < 4; rp++) {
            int re = row0 + rbase + 2 * rp;
            int ro = re + 1;
            float e0, o0, e1, o1, e2, o2, e3, o3;
            upk2(e0, o0, acc[rp][0]); upk2(e1, o1, acc[rp][1]);
            upk2(e2, o2, acc[rp][2]); upk2(e3, o3, acc[rp][3]);
            if (re < ND) {
                __half2 hh[2] = {__floats2half2_rn(e0 + b0, e1 + b1),
                                 __floats2half2_rn(e2 + b2, e3 + b3)};
                *(uint2*)(g_msgs + (size_t)re * DD + lane * 4) = *(uint2*)hh;
            }
            if (ro < ND) {
                __half2 hh[2] = {__floats2half2_rn(o0 + b0, o1 + b1),
                                 __floats2half2_rn(o2 + b2, o3 + b3)};
                *(uint2*)(g_msgs + (size_t)ro * DD + lane * 4) = *(uint2*)hh;
            }
        }
    }
}

// ------------------------------------------------------------------
// Fused gather + LayerNorm: one warp per protein row.
// fp16 payloads (8 B / lane / edge), fp32 accumulation.
// ------------------------------------------------------------------
__global__ __launch_bounds__(256) void k_gather_ln(float* __restrict__ out) {
    int c = blockIdx.x * 8 + (threadIdx.x >> 5);
    if (c >= NP) return;
    int lane = threadIdx.x & 31;

    // PPI aggregate over pre-scaled h1s (self term included)
    float4 acc = make_float4(0.f, 0.f, 0.f, 0.f);
    acc_h4(acc, __ldg((const uint2*)(g_h1s + (size_t)c * DD) + lane));

    int i = __ldg(g_pstart + c), e = __ldg(g_pstart + c + 1);
    for (; i + 7 < e; i += 8) {
        int r[8];
        uint2 u[8];
#pragma unroll
        for (int t = 0; t < 8; t++) r[t] = __ldg(g_plist + i + t);
#pragma unroll
        for (int t = 0; t < 8; t++)
            u[t] = __ldg((const uint2*)(g_h1s + (size_t)r[t] * DD) + lane);
#pragma unroll
        for (int t = 0; t < 8; t++) acc_h4(acc, u[t]);
    }
    for (; i < e; i++) {
        int r0 = __ldg(g_plist + i);
        acc_h4(acc, __ldg((const uint2*)(g_h1s + (size_t)r0 * DD) + lane));
    }

    // DTI aggregate
    float4 accB = make_float4(0.f, 0.f, 0.f, 0.f);
    i = __ldg(g_dstart + c); e = __ldg(g_dstart + c + 1);
    for (; i + 3 < e; i += 4) {
        int d[4];
        uint2 u[4];
#pragma unroll
        for (int t = 0; t < 4; t++) d[t] = __ldg(g_dlist + i + t);
#pragma unroll
        for (int t = 0; t < 4; t++)
            u[t] = __ldg((const uint2*)(g_msgs + (size_t)d[t] * DD) + lane);
#pragma unroll
        for (int t = 0; t < 4; t++) acc_h4(accB, u[t]);
    }
    for (; i < e; i++) {
        int d0 = __ldg(g_dlist + i);
        acc_h4(accB, __ldg((const uint2*)(g_msgs + (size_t)d0 * DD) + lane));
    }

    float dc = __ldg(g_dinv + c);
    float ci = __ldg(g_cinv + c);
    float4 h3 = __ldg((const float4*)(g_h3 + (size_t)c * DD) + lane);
    float4 y;
    y.x = dc * acc.x + ci * accB.x + h3.x;
    y.y = dc * acc.y + ci * accB.y + h3.y;
    y.z = dc * acc.z + ci * accB.z + h3.z;
    y.w = dc * acc.w + ci * accB.w + h3.w;

    // LayerNorm over the 32-lane row (lane owns 4 consecutive cols)
    float s = (y.x + y.y) + (y.z + y.w);
#pragma unroll
    for (int o = 16; o > 0; o >>= 1) s += __shfl_xor_sync(0xffffffffu, s, o);
    float mu = s * (1.0f / DD);
    float dx = y.x - mu, dy = y.y - mu, dz = y.z - mu, dw = y.w - mu;
    float q = (dx * dx + dy * dy) + (dz * dz + dw * dw);
#pragma unroll
    for (int o = 16; o > 0; o >>= 1) q += __shfl_xor_sync(0xffffffffu, q, o);
    float inv = rsqrtf(q * (1.0f / DD) + 1e-5f);
    float4 o4 = make_float4(dx * inv, dy * inv, dz * inv, dw * inv);
    ((float4*)(out + (size_t)c * DD))[lane] = o4;
}

// ------------------------------------------------------------------
extern "C" void kernel_launch(void* const* d_in, const int* in_sizes, int n_in,
                              void* d_out, int out_size) {
    const float* x_prot = (const float*)d_in[0];
    const float* x_drug = (const float*)d_in[1];
    const float* W_gcn  = (const float*)d_in[2];
    const float* b_gcn  = (const float*)d_in[3];
    const float* W_td   = (const float*)d_in[4];
    const float* b_td   = (const float*)d_in[5];
    const float* W_pr   = (const float*)d_in[6];
    const float* b_pr   = (const float*)d_in[7];
    const int*   ppi    = (const int*)d_in[8];   // [2, EP]: src = ppi, dst = ppi+EP
    const int*   dti_d  = (const int*)d_in[9];
    const int*   dti_p  = (const int*)d_in[10];
    float* out = (float*)d_out;

    k_count<<<(EP + ED + 255) / 256, 256>>>(ppi + EP, dti_p);            // 1
    k_scan1<<<NB, 256>>>();                                              // 2 (dinv/cinv here)
    k_scan2<<<1, 512>>>();                                               // 3
    k_mm<<<PRE_BLOCKS + DRUG_BLOCKS, 256>>>(x_prot, W_gcn, W_pr,         // 4 (profiled)
                                            b_gcn, b_pr, x_drug, W_td, b_td);
    k_scan3<<<NB, 256>>>();                                              // 5
    k_fill<<<(EP + ED + 255) / 256, 256>>>(ppi, ppi + EP, dti_d, dti_p); // 6
    k_gather_ln<<<(NP + 7) / 8, 256>>>(out);                             // 7
}